// round 15
// baseline (speedup 1.0000x reference)
#include <cuda_runtime.h>
#include <cstdint>

// CARAFE: features [2,64,64,128] f32 NHWC, masks [2,128,128,25] f32.
// Output [2,128,128,128] f32. k=5, G=1, Cg=128. 2x nearest: src = dst/2.
//
// Warp = 2 adjacent centers (bx, bx+1) -> 8 outputs, 5x6 union window:
// 30 feature LDG.128 serve 50 tap-uses. Softmax UNNORMALIZED in mainloop
// (weights = e, OOB taps = 0); accumulators scaled by 1/sum at the end.
// R15 deltas vs R14: 64-reg cap (8 blocks/SM -> 32 warps resident, was 28)
// enabled by splitting each row's 6-col load batch into 2x3 (peak feature
// liveness 12 regs, was 24); all 8 mask loads batched before softmax math.

#define FEAT_H 64
#define FEAT_W 64
#define OUT_H 128
#define OUT_W 128
#define C4 32
#define K 5
#define K2 25
#define WARPS 4
#define CPB 8            // centers per block

__global__ __launch_bounds__(32 * WARPS, 8)
void carafe_kernel(const float* __restrict__ feat,
                   const float* __restrict__ masks,
                   float* __restrict__ out)
{
    const int tid  = threadIdx.x;
    const int wid  = tid >> 5;
    const int lane = tid & 31;

    const int c0  = blockIdx.x * CPB + 2 * wid;   // even center id
    const int bxA = c0 & 63;                      // bxB = bxA + 1, same row
    const int by  = (c0 >> 6) & 63;
    const int b   = c0 >> 12;

    // weights (unnormalized e, paired): [center-in-block][tap][output]
    __shared__ __align__(16) float2 wsh[CPB][K2][4];
    const int idxA = 2 * wid;

    // ---- prologue: batch all 8 mask loads, then exp + shfl sums ----
    const int tdi = lane / K, tdj = lane % K;
    const int ty  = by + tdi - 2;
    const bool vy = ((unsigned)ty < (unsigned)FEAT_H);

    float mv[8];
    {
        const float* mbase =
            masks + (((size_t)b * OUT_H + 2 * by) * OUT_W + 2 * bxA) * K2;
        #pragma unroll
        for (int i = 0; i < 8; i++) {            // i = c*4 + o
            const int c = i >> 2, o = i & 3;
            const float* mp = mbase + ((size_t)(o >> 1) * OUT_W + (o & 1) + 2 * c) * K2;
            mv[i] = (lane < K2) ? __ldg(mp + lane) : 0.f;
        }
    }

    float sA[4], sB[4];
    #pragma unroll
    for (int c = 0; c < 2; c++) {
        const bool valid = vy &
            ((unsigned)(bxA + c + tdj - 2) < (unsigned)FEAT_W);
        #pragma unroll
        for (int o = 0; o < 4; o++) {
            // logits are N(0,1)-scale: exp cannot overflow
            float e = (lane < K2) ? __expf(mv[c * 4 + o]) : 0.f;
            float s = e;
            #pragma unroll
            for (int off = 16; off; off >>= 1)
                s += __shfl_xor_sync(0xffffffffu, s, off);
            if (c == 0) sA[o] = s; else sB[o] = s;
            if (lane < K2) {
                const float wv = valid ? e : 0.f;  // OOB tap -> 0 (ref zero-pads)
                wsh[idxA + c][lane][o] = make_float2(wv, wv);
            }
        }
    }
    __syncwarp();

    const uint32_t wbA = (uint32_t)__cvta_generic_to_shared(&wsh[idxA][0][0]);
    const uint32_t wbB = wbA + K2 * 32;

    // ---- mainloop: 5 rows x 6 union columns, 2x3 load batches ----
    const float4* fb = (const float4*)feat
                     + (size_t)b * FEAT_H * FEAT_W * C4 + lane;

    uint64_t aA00 = 0, aA01 = 0, aA10 = 0, aA11 = 0;
    uint64_t aA20 = 0, aA21 = 0, aA30 = 0, aA31 = 0;
    uint64_t aB00 = 0, aB01 = 0, aB10 = 0, aB11 = 0;
    uint64_t aB20 = 0, aB21 = 0, aB30 = 0, aB31 = 0;

    #pragma unroll
    for (int di = 0; di < K; di++) {
        const int y = min(max(by + di - 2, 0), FEAT_H - 1);
        const float4* frow = fb + (size_t)y * FEAT_W * C4;

        #pragma unroll
        for (int h = 0; h < 2; h++) {            // two half-batches of 3 cols
            uint64_t f0[3], f1[3];
            #pragma unroll
            for (int j = 0; j < 3; j++) {
                const int x = min(max(bxA + h * 3 + j - 2, 0), FEAT_W - 1);
                asm("ld.global.nc.v2.u64 {%0,%1}, [%2];"
                    : "=l"(f0[j]), "=l"(f1[j]) : "l"(frow + (size_t)x * C4));
            }
            #pragma unroll
            for (int j = 0; j < 3; j++) {
                const int u = h * 3 + j;
                if (u < 5) {                      // center A: tap (di, u)
                    const uint32_t wa = wbA + (di * K + u) * 32;
                    uint64_t w0, w1, w2, w3;
                    asm("ld.shared.v2.u64 {%0,%1}, [%2];" : "=l"(w0), "=l"(w1) : "r"(wa));
                    asm("ld.shared.v2.u64 {%0,%1}, [%2];" : "=l"(w2), "=l"(w3) : "r"(wa + 16));
                    asm("fma.rn.f32x2 %0, %1, %2, %0;" : "+l"(aA00) : "l"(w0), "l"(f0[j]));
                    asm("fma.rn.f32x2 %0, %1, %2, %0;" : "+l"(aA01) : "l"(w0), "l"(f1[j]));
                    asm("fma.rn.f32x2 %0, %1, %2, %0;" : "+l"(aA10) : "l"(w1), "l"(f0[j]));
                    asm("fma.rn.f32x2 %0, %1, %2, %0;" : "+l"(aA11) : "l"(w1), "l"(f1[j]));
                    asm("fma.rn.f32x2 %0, %1, %2, %0;" : "+l"(aA20) : "l"(w2), "l"(f0[j]));
                    asm("fma.rn.f32x2 %0, %1, %2, %0;" : "+l"(aA21) : "l"(w2), "l"(f1[j]));
                    asm("fma.rn.f32x2 %0, %1, %2, %0;" : "+l"(aA30) : "l"(w3), "l"(f0[j]));
                    asm("fma.rn.f32x2 %0, %1, %2, %0;" : "+l"(aA31) : "l"(w3), "l"(f1[j]));
                }
                if (u >= 1) {                     // center B: tap (di, u-1)
                    const uint32_t wa = wbB + (di * K + u - 1) * 32;
                    uint64_t w0, w1, w2, w3;
                    asm("ld.shared.v2.u64 {%0,%1}, [%2];" : "=l"(w0), "=l"(w1) : "r"(wa));
                    asm("ld.shared.v2.u64 {%0,%1}, [%2];" : "=l"(w2), "=l"(w3) : "r"(wa + 16));
                    asm("fma.rn.f32x2 %0, %1, %2, %0;" : "+l"(aB00) : "l"(w0), "l"(f0[j]));
                    asm("fma.rn.f32x2 %0, %1, %2, %0;" : "+l"(aB01) : "l"(w0), "l"(f1[j]));
                    asm("fma.rn.f32x2 %0, %1, %2, %0;" : "+l"(aB10) : "l"(w1), "l"(f0[j]));
                    asm("fma.rn.f32x2 %0, %1, %2, %0;" : "+l"(aB11) : "l"(w1), "l"(f1[j]));
                    asm("fma.rn.f32x2 %0, %1, %2, %0;" : "+l"(aB20) : "l"(w2), "l"(f0[j]));
                    asm("fma.rn.f32x2 %0, %1, %2, %0;" : "+l"(aB21) : "l"(w2), "l"(f1[j]));
                    asm("fma.rn.f32x2 %0, %1, %2, %0;" : "+l"(aB30) : "l"(w3), "l"(f0[j]));
                    asm("fma.rn.f32x2 %0, %1, %2, %0;" : "+l"(aB31) : "l"(w3), "l"(f1[j]));
                }
            }
        }
    }

    // ---- normalize: scale each output's accumulators by 1/sum ----
    #define SCALE2(acc0, acc1, s) do {                                   \
        const float _rs = __fdividef(1.f, (s));                          \
        uint64_t _rp;                                                    \
        asm("mov.b64 %0, {%1, %1};" : "=l"(_rp) : "f"(_rs));             \
        asm("mul.rn.f32x2 %0, %0, %1;" : "+l"(acc0) : "l"(_rp));         \
        asm("mul.rn.f32x2 %0, %0, %1;" : "+l"(acc1) : "l"(_rp));         \
    } while (0)

    SCALE2(aA00, aA01, sA[0]); SCALE2(aA10, aA11, sA[1]);
    SCALE2(aA20, aA21, sA[2]); SCALE2(aA30, aA31, sA[3]);
    SCALE2(aB00, aB01, sB[0]); SCALE2(aB10, aB11, sB[1]);
    SCALE2(aB20, aB21, sB[2]); SCALE2(aB30, aB31, sB[3]);

    // ---- write the two 2x2 output quads ----
    float4* __restrict__ o4 = (float4*)out;
    const size_t rs = (size_t)OUT_W * C4;
    float4* obA = o4 + (((size_t)b * OUT_H + 2 * by) * OUT_W + 2 * bxA) * C4 + lane;
    float4* obB = obA + 2 * C4;

    asm volatile("st.global.v2.u64 [%0], {%1,%2};"
                 :: "l"(obA),           "l"(aA00), "l"(aA01) : "memory");
    asm volatile("st.global.v2.u64 [%0], {%1,%2};"
                 :: "l"(obA + C4),      "l"(aA10), "l"(aA11) : "memory");
    asm volatile("st.global.v2.u64 [%0], {%1,%2};"
                 :: "l"(obA + rs),      "l"(aA20), "l"(aA21) : "memory");
    asm volatile("st.global.v2.u64 [%0], {%1,%2};"
                 :: "l"(obA + rs + C4), "l"(aA30), "l"(aA31) : "memory");
    asm volatile("st.global.v2.u64 [%0], {%1,%2};"
                 :: "l"(obB),           "l"(aB00), "l"(aB01) : "memory");
    asm volatile("st.global.v2.u64 [%0], {%1,%2};"
                 :: "l"(obB + C4),      "l"(aB10), "l"(aB11) : "memory");
    asm volatile("st.global.v2.u64 [%0], {%1,%2};"
                 :: "l"(obB + rs),      "l"(aB20), "l"(aB21) : "memory");
    asm volatile("st.global.v2.u64 [%0], {%1,%2};"
                 :: "l"(obB + rs + C4), "l"(aB30), "l"(aB31) : "memory");
}

extern "C" void kernel_launch(void* const* d_in, const int* in_sizes, int n_in,
                              void* d_out, int out_size)
{
    const float* feat  = (const float*)d_in[0];   // [2,64,64,128]
    const float* masks = (const float*)d_in[1];   // [2,128,128,25]
    float* out = (float*)d_out;                   // [2,128,128,128]

    const int n_centers = 2 * FEAT_H * FEAT_W;    // 8192
    carafe_kernel<<<n_centers / CPB, 32 * WARPS>>>(feat, masks, out);
}

// round 16
// speedup vs baseline: 1.1422x; 1.1422x over previous
#include <cuda_runtime.h>
#include <cstdint>

// CARAFE: features [2,64,64,128] f32 NHWC, masks [2,128,128,25] f32.
// Output [2,128,128,128] f32. k=5, G=1, Cg=128. 2x nearest: src = dst/2.
//
// R14 core (best: 13.0us), one change: the 4 warps of a block are 4
// VERTICALLY adjacent center-pairs (same bx pair, by = 4*gy + wid), so
// the 5x vertical reuse of feature rows happens within one SM's L1
// (hit ~32cy) instead of across blocks via L2 (~234cy).
//
// Warp = 2 adjacent centers (bxA, bxA+1) -> 8 outputs, 5x6 union window:
// 30 feature LDG.128 serve 50 tap-uses, batched 6/row (MLP=6). Softmax
// UNNORMALIZED in mainloop (weights = e, OOB taps = 0, matching the
// reference's zero-padding); accumulators scaled by 1/sum at the end.

#define FEAT_H 64
#define FEAT_W 64
#define OUT_H 128
#define OUT_W 128
#define C4 32
#define K 5
#define K2 25
#define WARPS 4
#define CPB 8

__global__ __launch_bounds__(32 * WARPS, 7)
void carafe_kernel(const float* __restrict__ feat,
                   const float* __restrict__ masks,
                   float* __restrict__ out)
{
    const int tid  = threadIdx.x;
    const int wid  = tid >> 5;
    const int lane = tid & 31;

    // block -> (b, gy, px): 32 x-pairs, 16 y-groups of 4, 2 batches
    const int px = blockIdx.x & 31;            // pair index: bxA = 2*px
    const int gy = (blockIdx.x >> 5) & 15;     // y-group
    const int b  = blockIdx.x >> 9;
    const int bxA = 2 * px;
    const int by  = 4 * gy + wid;              // warp = vertical neighbor

    // weights (unnormalized e, paired): [warp-slot][center 0/1][tap][output]
    __shared__ __align__(16) float2 wsh[WARPS][2][K2][4];

    // ---- prologue: mask loads -> exp -> store e-pairs; shfl sums ----
    const int tdi = lane / K, tdj = lane % K;
    const int ty  = by + tdi - 2;
    const bool vy = ((unsigned)ty < (unsigned)FEAT_H);

    float sA[4], sB[4];
    #pragma unroll
    for (int c = 0; c < 2; c++) {
        const int bx = bxA + c;
        const bool valid = vy & ((unsigned)(bx + tdj - 2) < (unsigned)FEAT_W);
        const float* mbase =
            masks + (((size_t)b * OUT_H + 2 * by) * OUT_W + 2 * bx) * K2;
        #pragma unroll
        for (int o = 0; o < 4; o++) {
            const float* mp = mbase + ((o >> 1) * (size_t)OUT_W + (o & 1)) * K2;
            // logits are N(0,1)-scale: exp cannot overflow
            float e = (lane < K2) ? __expf(__ldg(mp + lane)) : 0.f;
            float s = e;
            #pragma unroll
            for (int off = 16; off; off >>= 1)
                s += __shfl_xor_sync(0xffffffffu, s, off);
            if (c == 0) sA[o] = s; else sB[o] = s;
            if (lane < K2) {
                const float wv = valid ? e : 0.f;   // OOB tap -> 0
                wsh[wid][c][lane][o] = make_float2(wv, wv);
            }
        }
    }
    __syncwarp();

    const uint32_t wbA = (uint32_t)__cvta_generic_to_shared(&wsh[wid][0][0][0]);
    const uint32_t wbB = wbA + K2 * 32;

    // ---- mainloop: 5 rows x 6 union columns, 6-load batches ----
    const float4* fb = (const float4*)feat
                     + (size_t)b * FEAT_H * FEAT_W * C4 + lane;

    uint64_t aA00 = 0, aA01 = 0, aA10 = 0, aA11 = 0;
    uint64_t aA20 = 0, aA21 = 0, aA30 = 0, aA31 = 0;
    uint64_t aB00 = 0, aB01 = 0, aB10 = 0, aB11 = 0;
    uint64_t aB20 = 0, aB21 = 0, aB30 = 0, aB31 = 0;

    #pragma unroll
    for (int di = 0; di < K; di++) {
        const int y = min(max(by + di - 2, 0), FEAT_H - 1);
        const float4* frow = fb + (size_t)y * FEAT_W * C4;

        uint64_t f0[6], f1[6];
        #pragma unroll
        for (int u = 0; u < 6; u++) {
            const int x = min(max(bxA + u - 2, 0), FEAT_W - 1);
            asm("ld.global.nc.v2.u64 {%0,%1}, [%2];"
                : "=l"(f0[u]), "=l"(f1[u]) : "l"(frow + (size_t)x * C4));
        }

        #pragma unroll
        for (int u = 0; u < 6; u++) {
            if (u < 5) {                      // center A: tap (di, u)
                const uint32_t wa = wbA + (di * K + u) * 32;
                uint64_t w0, w1, w2, w3;
                asm("ld.shared.v2.u64 {%0,%1}, [%2];" : "=l"(w0), "=l"(w1) : "r"(wa));
                asm("ld.shared.v2.u64 {%0,%1}, [%2];" : "=l"(w2), "=l"(w3) : "r"(wa + 16));
                asm("fma.rn.f32x2 %0, %1, %2, %0;" : "+l"(aA00) : "l"(w0), "l"(f0[u]));
                asm("fma.rn.f32x2 %0, %1, %2, %0;" : "+l"(aA01) : "l"(w0), "l"(f1[u]));
                asm("fma.rn.f32x2 %0, %1, %2, %0;" : "+l"(aA10) : "l"(w1), "l"(f0[u]));
                asm("fma.rn.f32x2 %0, %1, %2, %0;" : "+l"(aA11) : "l"(w1), "l"(f1[u]));
                asm("fma.rn.f32x2 %0, %1, %2, %0;" : "+l"(aA20) : "l"(w2), "l"(f0[u]));
                asm("fma.rn.f32x2 %0, %1, %2, %0;" : "+l"(aA21) : "l"(w2), "l"(f1[u]));
                asm("fma.rn.f32x2 %0, %1, %2, %0;" : "+l"(aA30) : "l"(w3), "l"(f0[u]));
                asm("fma.rn.f32x2 %0, %1, %2, %0;" : "+l"(aA31) : "l"(w3), "l"(f1[u]));
            }
            if (u >= 1) {                     // center B: tap (di, u-1)
                const uint32_t wa = wbB + (di * K + u - 1) * 32;
                uint64_t w0, w1, w2, w3;
                asm("ld.shared.v2.u64 {%0,%1}, [%2];" : "=l"(w0), "=l"(w1) : "r"(wa));
                asm("ld.shared.v2.u64 {%0,%1}, [%2];" : "=l"(w2), "=l"(w3) : "r"(wa + 16));
                asm("fma.rn.f32x2 %0, %1, %2, %0;" : "+l"(aB00) : "l"(w0), "l"(f0[u]));
                asm("fma.rn.f32x2 %0, %1, %2, %0;" : "+l"(aB01) : "l"(w0), "l"(f1[u]));
                asm("fma.rn.f32x2 %0, %1, %2, %0;" : "+l"(aB10) : "l"(w1), "l"(f0[u]));
                asm("fma.rn.f32x2 %0, %1, %2, %0;" : "+l"(aB11) : "l"(w1), "l"(f1[u]));
                asm("fma.rn.f32x2 %0, %1, %2, %0;" : "+l"(aB20) : "l"(w2), "l"(f0[u]));
                asm("fma.rn.f32x2 %0, %1, %2, %0;" : "+l"(aB21) : "l"(w2), "l"(f1[u]));
                asm("fma.rn.f32x2 %0, %1, %2, %0;" : "+l"(aB30) : "l"(w3), "l"(f0[u]));
                asm("fma.rn.f32x2 %0, %1, %2, %0;" : "+l"(aB31) : "l"(w3), "l"(f1[u]));
            }
        }
    }

    // ---- normalize: scale each output's accumulators by 1/sum ----
    #define SCALE2(acc0, acc1, s) do {                                   \
        const float _rs = __fdividef(1.f, (s));                          \
        uint64_t _rp;                                                    \
        asm("mov.b64 %0, {%1, %1};" : "=l"(_rp) : "f"(_rs));             \
        asm("mul.rn.f32x2 %0, %0, %1;" : "+l"(acc0) : "l"(_rp));         \
        asm("mul.rn.f32x2 %0, %0, %1;" : "+l"(acc1) : "l"(_rp));         \
    } while (0)

    SCALE2(aA00, aA01, sA[0]); SCALE2(aA10, aA11, sA[1]);
    SCALE2(aA20, aA21, sA[2]); SCALE2(aA30, aA31, sA[3]);
    SCALE2(aB00, aB01, sB[0]); SCALE2(aB10, aB11, sB[1]);
    SCALE2(aB20, aB21, sB[2]); SCALE2(aB30, aB31, sB[3]);

    // ---- write the two 2x2 output quads ----
    float4* __restrict__ o4 = (float4*)out;
    const size_t rs = (size_t)OUT_W * C4;
    float4* obA = o4 + (((size_t)b * OUT_H + 2 * by) * OUT_W + 2 * bxA) * C4 + lane;
    float4* obB = obA + 2 * C4;

    asm volatile("st.global.v2.u64 [%0], {%1,%2};"
                 :: "l"(obA),           "l"(aA00), "l"(aA01) : "memory");
    asm volatile("st.global.v2.u64 [%0], {%1,%2};"
                 :: "l"(obA + C4),      "l"(aA10), "l"(aA11) : "memory");
    asm volatile("st.global.v2.u64 [%0], {%1,%2};"
                 :: "l"(obA + rs),      "l"(aA20), "l"(aA21) : "memory");
    asm volatile("st.global.v2.u64 [%0], {%1,%2};"
                 :: "l"(obA + rs + C4), "l"(aA30), "l"(aA31) : "memory");
    asm volatile("st.global.v2.u64 [%0], {%1,%2};"
                 :: "l"(obB),           "l"(aB00), "l"(aB01) : "memory");
    asm volatile("st.global.v2.u64 [%0], {%1,%2};"
                 :: "l"(obB + C4),      "l"(aB10), "l"(aB11) : "memory");
    asm volatile("st.global.v2.u64 [%0], {%1,%2};"
                 :: "l"(obB + rs),      "l"(aB20), "l"(aB21) : "memory");
    asm volatile("st.global.v2.u64 [%0], {%1,%2};"
                 :: "l"(obB + rs + C4), "l"(aB30), "l"(aB31) : "memory");
}

extern "C" void kernel_launch(void* const* d_in, const int* in_sizes, int n_in,
                              void* d_out, int out_size)
{
    const float* feat  = (const float*)d_in[0];   // [2,64,64,128]
    const float* masks = (const float*)d_in[1];   // [2,128,128,25]
    float* out = (float*)d_out;                   // [2,128,128,128]

    const int n_centers = 2 * FEAT_H * FEAT_W;    // 8192
    carafe_kernel<<<n_centers / CPB, 32 * WARPS>>>(feat, masks, out);
}